// round 12
// baseline (speedup 1.0000x reference)
#include <cuda_runtime.h>

#define E_TOTAL 1600000
#define N_NODES 50000
#define MAX_DEG 160

#define FSCALE     0.17677669529663687f  // 1/sqrt(32)
#define FINV_SQRT3 0.57735026918962576f  // 1/sqrt(3)

__device__ int    g_cnt[N_NODES];
__device__ int    g_sender[(size_t)N_NODES * MAX_DEG];
__device__ float4 g_rec[(size_t)N_NODES * MAX_DEG * 3];  // {h0..3, h4..7, ef}
__device__ float4 g_nodes4[N_NODES * 8];                 // node -> 8 x {s_m, v0, v1, v2}

// Fused: zero per-node counters + transpose node_feats into per-m float4
__global__ void k_init(const float* __restrict__ node_feats) {
    int i = blockIdx.x * blockDim.x + threadIdx.x;   // node*8 + m
    if (i < N_NODES) g_cnt[i] = 0;
    if (i >= N_NODES * 8) return;
    int node = i >> 3;
    int m    = i & 7;
    const float* nf = node_feats + node * 32;
    g_nodes4[i] = make_float4(__ldg(nf + m),
                              __ldg(nf + 8 + 3 * m),
                              __ldg(nf + 9 + 3 * m),
                              __ldg(nf + 10 + 3 * m));
}

// Edge-parallel: hidden MLP + bucket append. Coalesced reads, scattered writes.
__global__ __launch_bounds__(256) void k_fill_hidden(
    const int*    __restrict__ senders,
    const int*    __restrict__ receivers,
    const float4* __restrict__ radial,
    const float4* __restrict__ edge_features,
    const float*  __restrict__ w1)
{
    __shared__ float sw1[64];
    int t = threadIdx.x;
    if (t < 64) sw1[t] = w1[t];
    __syncthreads();

    int e = blockIdx.x * 256 + t;
    if (e >= E_TOTAL) return;

    float4 r0 = __ldg(&radial[2 * e]);
    float4 r1 = __ldg(&radial[2 * e + 1]);
    float4 ef = __ldg(&edge_features[e]);
    int   snd = __ldg(&senders[e]);
    int   rcv = __ldg(&receivers[e]);

    float r[8] = {r0.x, r0.y, r0.z, r0.w, r1.x, r1.y, r1.z, r1.w};
    float h[8];
    #pragma unroll
    for (int j = 0; j < 8; j++) {
        float acc = 0.f;
        #pragma unroll
        for (int i = 0; i < 8; i++) acc = fmaf(r[i], sw1[i * 8 + j], acc);
        h[j] = acc * (FSCALE / (1.f + __expf(-acc)));
    }

    int pos = atomicAdd(&g_cnt[rcv], 1);
    size_t base = (size_t)rcv * MAX_DEG + pos;
    g_sender[base]      = snd;
    g_rec[3 * base]     = make_float4(h[0], h[1], h[2], h[3]);
    g_rec[3 * base + 1] = make_float4(h[4], h[5], h[6], h[7]);
    g_rec[3 * base + 2] = ef;
}

// One block (4 warps) per node; warp takes 1/4 of segment.
// Lane l (<24) owns scal[l], vec[l][0..2]. 5 loads/edge, no shuffles.
#define EDGE_BODY(KK)                                                         \
    {                                                                         \
        int snd = g_sender[(KK)];                                             \
        float4 nd = g_nodes4[snd * 8 + mm];                                   \
        float4 h0 = g_rec[3 * (size_t)(KK)];                                  \
        float4 h1 = g_rec[3 * (size_t)(KK) + 1];                              \
        float4 ef = g_rec[3 * (size_t)(KK) + 2];                              \
        float s = nd.x, v0 = nd.y, v1 = nd.z, v2 = nd.w;                      \
        float e0 = ef.x, e1x = ef.y, e1y = ef.z, e1z = ef.w;                  \
        float wa, wb;                                                         \
        wa = fmaf(h0.x, w2A[0], fmaf(h0.y, w2A[1],                            \
             fmaf(h0.z, w2A[2], h0.w * w2A[3])));                             \
        wa = fmaf(h1.x, w2A[4], fmaf(h1.y, w2A[5],                            \
             fmaf(h1.z, w2A[6], fmaf(h1.w, w2A[7], wa))));                    \
        wb = fmaf(h0.x, w2B[0], fmaf(h0.y, w2B[1],                            \
             fmaf(h0.z, w2B[2], h0.w * w2B[3])));                             \
        wb = fmaf(h1.x, w2B[4], fmaf(h1.y, w2B[5],                            \
             fmaf(h1.z, w2B[6], fmaf(h1.w, w2B[7], wb))));                    \
        float eS   = g0 ? 1.f : (g1 ? e0 : 0.f);                              \
        float dsel = g2 ? 1.f : 0.f;                                          \
        float dot  = fmaf(v0, e1x, fmaf(v1, e1y, v2 * e1z));                  \
        float scal_inner = fmaf(s, eS, dot * dsel);                           \
        float fV  = g0 ? 1.f : (g2 ? e0 : 0.f);                               \
        float sfs = s * fS;                                                   \
        float i0 = fmaf(v0, fV, sfs * e1x);                                   \
        float i1 = fmaf(v1, fV, sfs * e1y);                                   \
        float i2 = fmaf(v2, fV, sfs * e1z);                                   \
        acc_s  = fmaf(scal_inner, wa, acc_s);                                 \
        acc_v0 = fmaf(i0, wb, acc_v0);                                        \
        acc_v1 = fmaf(i1, wb, acc_v1);                                        \
        acc_v2 = fmaf(i2, wb, acc_v2);                                        \
    }

__global__ __launch_bounds__(128) void k_gather(
    const float* __restrict__ w2,
    float*       __restrict__ out)
{
    __shared__ float red[4][96];

    int node = blockIdx.x;
    int lane = threadIdx.x & 31;
    int wi   = threadIdx.x >> 5;
    int mm   = lane & 7;

    bool g0 = lane < 8;
    bool g1 = (lane >= 8) && (lane < 16);
    bool g2 = (lane >= 16) && (lane < 24);
    int  cA = (lane < 24) ? lane : 0;
    float fS = g1 ? 1.f : 0.f;
    float sA = g2 ? FINV_SQRT3 : 1.f;

    float w2A[8], w2B[8];
    #pragma unroll
    for (int j = 0; j < 8; j++) {
        w2A[j] = __ldg(&w2[j * 48 + cA]) * sA;
        w2B[j] = __ldg(&w2[j * 48 + 24 + cA]);
    }

    int len = g_cnt[node];
    size_t beg = (size_t)node * MAX_DEG;
    size_t lo  = beg + (len * wi)       / 4;
    size_t hi  = beg + (len * (wi + 1)) / 4;

    float acc_s = 0.f, acc_v0 = 0.f, acc_v1 = 0.f, acc_v2 = 0.f;

    size_t k = lo;
    #pragma unroll 1
    for (; k + 1 < hi; k += 2) {
        EDGE_BODY(k)
        EDGE_BODY(k + 1)
    }
    if (k < hi) EDGE_BODY(k)

    if (lane < 24) {
        red[wi][lane]              = acc_s;
        red[wi][24 + 3 * lane]     = acc_v0;
        red[wi][24 + 3 * lane + 1] = acc_v1;
        red[wi][24 + 3 * lane + 2] = acc_v2;
    }
    __syncthreads();

    int t = threadIdx.x;
    if (t < 96) {
        out[(size_t)node * 96 + t] = red[0][t] + red[1][t] + red[2][t] + red[3][t];
    }
}

extern "C" void kernel_launch(void* const* d_in, const int* in_sizes, int n_in,
                              void* d_out, int out_size) {
    const float*  node_feats    = (const float*)d_in[0];
    const float4* edge_features = (const float4*)d_in[1];
    const float4* radial        = (const float4*)d_in[2];
    const float*  w1            = (const float*)d_in[3];
    const float*  w2            = (const float*)d_in[4];
    const int*    senders       = (const int*)d_in[5];
    const int*    receivers     = (const int*)d_in[6];
    float* out = (float*)d_out;

    k_init<<<(N_NODES * 8 + 255) / 256, 256>>>(node_feats);
    k_fill_hidden<<<(E_TOTAL + 255) / 256, 256>>>(senders, receivers, radial,
                                                  edge_features, w1);
    k_gather<<<N_NODES, 128>>>(w2, out);
}